// round 15
// baseline (speedup 1.0000x reference)
#include <cuda_runtime.h>
#include <cuda_fp16.h>
#include <cuda_bf16.h>
#include <cstdint>
#include <math.h>
#include <mma.h>

using namespace nvcuda;

#define BATCH 8
#define SEQ   2048
#define DIM   512
#define MR    (BATCH*SEQ)
#define HALF  (DIM/2)

// ---------------- static scratch ----------------
__device__ __half g_xh[(size_t)MR*DIM];         // x fp16 (im2col source + final acc)
__device__ __half g_wch[3*DIM*DIM];             // conv weights [dout][k=1536] K-major fp16
__device__ __half g_wqkvh[3*DIM*DIM];           // concat(Wq,Wk,Wv) [e=1536][d=512] fp16
__device__ __half g_xconvh[(size_t)MR*DIM];     // conv output fp16 (pre-bias)
__device__ __half g_xnorm[(size_t)MR*DIM];      // rmsnorm(conv+bias) fp16
__device__ __half g_qkvh[(size_t)MR*3*DIM];     // raw q|k|v fp16
__device__ __half g_q[(size_t)MR*DIM];          // normed+rope'd q fp16
__device__ __half g_k[(size_t)MR*DIM];          // normed+rope'd k fp16
__device__ __half g_v[(size_t)MR*DIM];          // v fp16
__device__ __nv_bfloat16 g_expsb[(size_t)BATCH*SEQ*SEQ]; // exp(logit) bf16
__device__ float  g_Z[MR];                      // row sums of exp
__device__ float  g_wbar[MR];
__device__ float  g_cos[SEQ*HALF];
__device__ float  g_sin[SEQ*HALF];
__device__ float  g_part[BATCH*16*DIM];

// ---------------- helpers ----------------
__device__ __forceinline__ uint32_t smem_u32(const void* p){
    uint32_t a;
    asm("{ .reg .u64 t; cvta.to.shared.u64 t, %1; cvt.u32.u64 %0, t; }" : "=r"(a) : "l"(p));
    return a;
}
__device__ __forceinline__ void cp_async16(uint32_t dst, const void* src, bool pred){
    int sz = pred ? 16 : 0;   // ZFILL when masked
    asm volatile("cp.async.cg.shared.global [%0], [%1], 16, %2;"
                 :: "r"(dst), "l"(src), "r"(sz));
}
__device__ __forceinline__ void cp_async_commit(){
    asm volatile("cp.async.commit_group;" ::: "memory");
}
template<int N>
__device__ __forceinline__ void cp_async_wait(){
    asm volatile("cp.async.wait_group %0;" :: "n"(N) : "memory");
}
__device__ __forceinline__ float warp_sum(float v){
    #pragma unroll
    for (int o=16;o;o>>=1) v += __shfl_xor_sync(0xffffffffu, v, o);
    return v;
}
// FMA-pipe exp. |rel err| ~2e-5.
__device__ __forceinline__ float fast_exp(float x){
    float t = x * 1.4426950408889634f;
    t = fmaxf(t, -125.0f);
    float fl = floorf(t);
    float f = t - fl;
    float p = 1.5403530e-4f;
    p = fmaf(p, f, 1.3333558e-3f);
    p = fmaf(p, f, 9.6181291e-3f);
    p = fmaf(p, f, 5.5504109e-2f);
    p = fmaf(p, f, 2.4022651e-1f);
    p = fmaf(p, f, 6.9314718e-1f);
    p = fmaf(p, f, 1.0f);
    int i = (int)fl;
    return p * __int_as_float((i + 127) << 23);
}

// ---------------- merged setup: x-convert | weight prep | rope tables ----------------
// Blocks [0,4096): cvt_x (+ zero wbar/Z). [4096,7168): weight re-layout.
// [7168,9216): rope tables (per-thread fp64 pow + double range reduction + float sincos).
#define SETUP_CVT   4096
#define SETUP_PREP  3072
#define SETUP_ROPE  2048
#define SETUP_BLKS  (SETUP_CVT + SETUP_PREP + SETUP_ROPE)

__global__ void setup_k(const float* __restrict__ x,
                        const float* __restrict__ conv_w,
                        const float* __restrict__ Wq,
                        const float* __restrict__ Wk,
                        const float* __restrict__ Wv)
{
    int bid = blockIdx.x;
    int tid = threadIdx.x;
    if (bid < SETUP_CVT) {
        size_t flat = (size_t)bid*256 + tid;
        size_t i = flat * 8;
        float4 v0 = *(const float4*)&x[i];
        float4 v1 = *(const float4*)&x[i+4];
        __half2 h[4] = { __floats2half2_rn(v0.x,v0.y), __floats2half2_rn(v0.z,v0.w),
                         __floats2half2_rn(v1.x,v1.y), __floats2half2_rn(v1.z,v1.w) };
        *(uint4*)&g_xh[i] = *(uint4*)h;
        if (flat < MR) { g_wbar[flat] = 0.f; g_Z[flat] = 0.f; }
    } else if (bid < SETUP_CVT + SETUP_PREP) {
        int idx = (bid - SETUP_CVT)*256 + tid;
        {   // conv: [dout][kk], kk = t*512 + din
            int kk   = idx % (3*DIM);
            int dout = idx / (3*DIM);
            int din  = kk % DIM;
            int t    = kk / DIM;
            g_wch[idx] = __float2half_rn(conv_w[(dout*DIM + din)*3 + t]);
        }
        {   // qkv concat
            float w = (idx < DIM*DIM) ? Wq[idx]
                    : (idx < 2*DIM*DIM) ? Wk[idx - DIM*DIM]
                    : Wv[idx - 2*DIM*DIM];
            g_wqkvh[idx] = __float2half_rn(w);
        }
    } else {
        int s = bid - (SETUP_CVT + SETUP_PREP);   // 0..2047
        int i = tid;                               // 0..255
        double inv = pow(10000.0, -((double)(2*i)) / 512.0);
        double arg = (double)s * inv;
        const double TWO_PI = 6.283185307179586476925;
        double red = arg - rint(arg * (1.0/TWO_PI)) * TWO_PI;   // [-pi, pi]
        float rf = (float)red;
        float sn, cs;
        __sincosf(rf, &sn, &cs);
        g_cos[s*HALF + i] = cs;
        g_sin[s*HALF + i] = sn;
    }
}

// ---------------- fp16 WMMA GEMM: block 128x256x32, warp tile 64x64 ----------------
// C[M,N] = A[M,K] * B[N,K]^T, f32 accumulate.
// MODE 0: generic (fp16 C).  MODE 1: A = implicit im2col (conv, fp16 C).
// MODE 2: batched via z; epilogue computes exp(scale*acc), stores bf16, row-sums into g_Z.
#define TLDH   40
#define A_BYT  (128*TLDH*2)          // 10240
#define STG_B  ((128+256)*TLDH*2)    // 30720
#define ELD    260                   // epilogue f32 tile ld (64 x 260 x 4 = 66560)
#define GSMEM  (3*STG_B)             // 92160

template<int MODE>
__global__ __launch_bounds__(256,1) void mma_gemm_k(
    const __half* __restrict__ Ah, const __half* __restrict__ Bh,
    __half* __restrict__ Ch, int Nd, int Kd, float scale)
{
    extern __shared__ __half smh[];
    const uint32_t sb = smem_u32(smh);
    const int tid = threadIdx.x;
    const int wid = tid >> 5, lane = tid & 31;
    const int wm = wid & 1, wn = wid >> 1;           // 2 x 4 warps, warp tile 64x64
    const int bm = blockIdx.y*128, bn = blockIdx.x*256;
    float* Zp = nullptr;
    if (MODE == 2) {
        size_t z = blockIdx.z;
        Ah += z * (size_t)SEQ * DIM;
        Bh += z * (size_t)SEQ * DIM;
        Ch += z * (size_t)SEQ * SEQ;
        Zp = g_Z + z * SEQ;
    }

    wmma::fragment<wmma::accumulator,16,16,16,float> acc[4][4];
    #pragma unroll
    for (int i=0;i<4;i++)
        #pragma unroll
        for (int j=0;j<4;j++) wmma::fill_fragment(acc[i][j], 0.f);

    const int nIter = Kd / 32;

    auto load_tiles = [&](int it, int stg){
        const int k0 = it*32;
        const uint32_t abase = sb + stg*STG_B;
        const uint32_t bbase = abase + A_BYT;
        // A: 128 rows x 32 halfs
        #pragma unroll
        for (int l=0;l<2;l++){
            int i   = l*256 + tid;
            int row = i >> 2;
            int kq  = (i & 3) * 8;
            const __half* src; bool pred = true;
            if (MODE == 1) {
                int gm = bm + row;
                int s  = gm & (SEQ-1);
                int kg = k0 + kq;
                int t  = kg >> 9;
                pred = !((s==0 && t==0) || (s==SEQ-1 && t==2));
                src = pred ? (Ah + (size_t)gm*DIM + kg - DIM) : Ah;
            } else {
                src = Ah + (size_t)(bm+row)*Kd + k0 + kq;
            }
            cp_async16(abase + (row*TLDH + kq)*2, src, pred);
        }
        // B: 256 rows x 32 halfs
        #pragma unroll
        for (int l=0;l<4;l++){
            int i   = l*256 + tid;
            int row = i >> 2;
            int kq  = (i & 3) * 8;
            cp_async16(bbase + (row*TLDH + kq)*2,
                       Bh + (size_t)(bn+row)*Kd + k0 + kq, true);
        }
    };

    load_tiles(0, 0); cp_async_commit();
    load_tiles(1, 1); cp_async_commit();

    for (int it = 0; it < nIter; ++it) {
        cp_async_wait<1>();
        __syncthreads();
        const int stg = it % 3;
        const __half* Ab = smh + stg*(STG_B/2);
        const __half* Bb = Ab + 128*TLDH;
        #pragma unroll
        for (int ks = 0; ks < 2; ks++) {
            wmma::fragment<wmma::matrix_b,16,16,16,__half,wmma::col_major> bf[4];
            #pragma unroll
            for (int j=0;j<4;j++)
                wmma::load_matrix_sync(bf[j], Bb + (wn*64 + j*16)*TLDH + ks*16, TLDH);
            #pragma unroll
            for (int i=0;i<4;i++){
                wmma::fragment<wmma::matrix_a,16,16,16,__half,wmma::row_major> af;
                wmma::load_matrix_sync(af, Ab + (wm*64 + i*16)*TLDH + ks*16, TLDH);
                #pragma unroll
                for (int j=0;j<4;j++)
                    wmma::mma_sync(acc[i][j], af, bf[j], acc[i][j]);
            }
        }
        if (it + 2 < nIter) load_tiles(it+2, (it+2)%3);
        cp_async_commit();
    }

    // epilogue via 64x260 f32 smem tile, two M-half passes
    cp_async_wait<0>();
    __syncthreads();
    float* eb = (float*)smh;
    #pragma unroll
    for (int h=0; h<2; h++){
        if (wm == h) {
            #pragma unroll
            for (int i=0;i<4;i++)
                #pragma unroll
                for (int j=0;j<4;j++)
                    wmma::store_matrix_sync(eb + (i*16)*ELD + wn*64 + j*16,
                                            acc[i][j], ELD, wmma::mem_row_major);
        }
        __syncthreads();
        #pragma unroll
        for (int p=0;p<8;p++){
            int e = p*256 + tid;          // 0..2047 chunks of 8 cols
            int row = e >> 5;             // tid 0..31 of each warp share one row
            int c0 = (e & 31) * 8;
            float4 a = *(float4*)&eb[row*ELD + c0];
            float4 b = *(float4*)&eb[row*ELD + c0 + 4];
            if (MODE == 2) {
                float ev[8] = { fast_exp(a.x*scale), fast_exp(a.y*scale),
                                fast_exp(a.z*scale), fast_exp(a.w*scale),
                                fast_exp(b.x*scale), fast_exp(b.y*scale),
                                fast_exp(b.z*scale), fast_exp(b.w*scale) };
                float s = ev[0]+ev[1]+ev[2]+ev[3]+ev[4]+ev[5]+ev[6]+ev[7];
                s = warp_sum(s);
                if (lane == 0) atomicAdd(&Zp[bm + h*64 + row], s);
                __nv_bfloat162 bb[4] = {
                    __floats2bfloat162_rn(ev[0],ev[1]), __floats2bfloat162_rn(ev[2],ev[3]),
                    __floats2bfloat162_rn(ev[4],ev[5]), __floats2bfloat162_rn(ev[6],ev[7]) };
                *(uint4*)&Ch[(size_t)(bm + h*64 + row)*Nd + bn + c0] = *(uint4*)bb;
            } else {
                __half2 hh[4] = { __floats2half2_rn(a.x,a.y), __floats2half2_rn(a.z,a.w),
                                  __floats2half2_rn(b.x,b.y), __floats2half2_rn(b.z,b.w) };
                *(uint4*)&Ch[(size_t)(bm + h*64 + row)*Nd + bn + c0] = *(uint4*)hh;
            }
        }
        __syncthreads();
    }
}

// ---------------- rmsnorm(conv + bias) -> fp16, warp per row ----------------
__global__ void rmsnorm_pre_k(const float* __restrict__ pre_g,
                              const float* __restrict__ conv_b)
{
    int row  = blockIdx.x*8 + (threadIdx.x >> 5);
    int lane = threadIdx.x & 31;
    const __half* r = g_xconvh + (size_t)row*DIM + lane*16;
    uint4 u0 = *(const uint4*)r;
    uint4 u1 = *(const uint4*)(r + 8);
    float4 b0 = *(const float4*)&conv_b[lane*16];
    float4 b1 = *(const float4*)&conv_b[lane*16+4];
    float4 b2 = *(const float4*)&conv_b[lane*16+8];
    float4 b3 = *(const float4*)&conv_b[lane*16+12];
    __half2* h0 = (__half2*)&u0;
    __half2* h1 = (__half2*)&u1;
    float v[16];
    #pragma unroll
    for (int i=0;i<4;i++){
        float2 f = __half22float2(h0[i]); v[2*i]=f.x; v[2*i+1]=f.y;
        float2 g = __half22float2(h1[i]); v[8+2*i]=g.x; v[8+2*i+1]=g.y;
    }
    float bias[16] = {b0.x,b0.y,b0.z,b0.w,b1.x,b1.y,b1.z,b1.w,
                      b2.x,b2.y,b2.z,b2.w,b3.x,b3.y,b3.z,b3.w};
    float ss = 0.f;
    #pragma unroll
    for (int i=0;i<16;i++){ v[i] += bias[i]; ss += v[i]*v[i]; }
    ss = warp_sum(ss);
    float rr = rsqrtf(ss * (1.f/DIM) + 1e-6f);
    float4 g0 = *(const float4*)&pre_g[lane*16];
    float4 g1 = *(const float4*)&pre_g[lane*16+4];
    float4 g2 = *(const float4*)&pre_g[lane*16+8];
    float4 g3 = *(const float4*)&pre_g[lane*16+12];
    float gg[16] = {g0.x,g0.y,g0.z,g0.w,g1.x,g1.y,g1.z,g1.w,
                    g2.x,g2.y,g2.z,g2.w,g3.x,g3.y,g3.z,g3.w};
    __half2 o[8];
    #pragma unroll
    for (int i=0;i<8;i++)
        o[i] = __floats2half2_rn(v[2*i]*rr*gg[2*i], v[2*i+1]*rr*gg[2*i+1]);
    __half* w = g_xnorm + (size_t)row*DIM + lane*16;
    *(uint4*)w       = *(uint4*)&o[0];
    *(uint4*)(w + 8) = *(uint4*)&o[4];
}

// ---------------- rmsnorm + rope on q/k -> fp16, v passthrough; warp per row ----------------
__global__ void qkv_post_k(const float* __restrict__ q_g, const float* __restrict__ k_g)
{
    int row  = blockIdx.x*8 + (threadIdx.x >> 5);
    int lane = threadIdx.x & 31;
    int s = row & (SEQ-1);
    const __half* r = g_qkvh + (size_t)row*3*DIM + lane*16;
    uint4 q0 = *(const uint4*)r;
    uint4 q1 = *(const uint4*)(r + 8);
    uint4 k0 = *(const uint4*)(r + DIM);
    uint4 k1 = *(const uint4*)(r + DIM + 8);
    uint4 v0 = *(const uint4*)(r + 2*DIM);
    uint4 v1 = *(const uint4*)(r + 2*DIM + 8);
    float q[16], k[16];
    {
        __half2* hq0=(__half2*)&q0; __half2* hq1=(__half2*)&q1;
        __half2* hk0=(__half2*)&k0; __half2* hk1=(__half2*)&k1;
        #pragma unroll
        for (int i=0;i<4;i++){
            float2 f;
            f=__half22float2(hq0[i]); q[2*i]=f.x; q[2*i+1]=f.y;
            f=__half22float2(hq1[i]); q[8+2*i]=f.x; q[8+2*i+1]=f.y;
            f=__half22float2(hk0[i]); k[2*i]=f.x; k[2*i+1]=f.y;
            f=__half22float2(hk1[i]); k[8+2*i]=f.x; k[8+2*i+1]=f.y;
        }
    }
    float sq=0.f, sk=0.f;
    #pragma unroll
    for (int i=0;i<16;i++){ sq += q[i]*q[i]; sk += k[i]*k[i]; }
    sq = warp_sum(sq); sk = warp_sum(sk);
    float rq = rsqrtf(sq * (1.f/DIM) + 1e-6f);
    float rk = rsqrtf(sk * (1.f/DIM) + 1e-6f);

    float4 c0 = *(const float4*)&g_cos[s*HALF + lane*8];
    float4 c1 = *(const float4*)&g_cos[s*HALF + lane*8 + 4];
    float4 s0 = *(const float4*)&g_sin[s*HALF + lane*8];
    float4 s1 = *(const float4*)&g_sin[s*HALF + lane*8 + 4];
    float cs[8] = {c0.x,c0.y,c0.z,c0.w,c1.x,c1.y,c1.z,c1.w};
    float sn[8] = {s0.x,s0.y,s0.z,s0.w,s1.x,s1.y,s1.z,s1.w};
    float4 qg0 = *(const float4*)&q_g[lane*16];
    float4 qg1 = *(const float4*)&q_g[lane*16+4];
    float4 qg2 = *(const float4*)&q_g[lane*16+8];
    float4 qg3 = *(const float4*)&q_g[lane*16+12];
    float4 kg0 = *(const float4*)&k_g[lane*16];
    float4 kg1 = *(const float4*)&k_g[lane*16+4];
    float4 kg2 = *(const float4*)&k_g[lane*16+8];
    float4 kg3 = *(const float4*)&k_g[lane*16+12];
    float qg[16] = {qg0.x,qg0.y,qg0.z,qg0.w,qg1.x,qg1.y,qg1.z,qg1.w,
                    qg2.x,qg2.y,qg2.z,qg2.w,qg3.x,qg3.y,qg3.z,qg3.w};
    float kg[16] = {kg0.x,kg0.y,kg0.z,kg0.w,kg1.x,kg1.y,kg1.z,kg1.w,
                    kg2.x,kg2.y,kg2.z,kg2.w,kg3.x,kg3.y,kg3.z,kg3.w};

    __half2 qo[8], ko[8];
    #pragma unroll
    for (int j=0;j<8;j++){
        float x0 = q[2*j]*rq*qg[2*j], x1 = q[2*j+1]*rq*qg[2*j+1];
        qo[j] = __floats2half2_rn(x0*cs[j] - x1*sn[j], x0*sn[j] + x1*cs[j]);
        float y0 = k[2*j]*rk*kg[2*j], y1 = k[2*j+1]*rk*kg[2*j+1];
        ko[j] = __floats2half2_rn(y0*cs[j] - y1*sn[j], y0*sn[j] + y1*cs[j]);
    }
    __half* wq = g_q + (size_t)row*DIM + lane*16;
    __half* wk = g_k + (size_t)row*DIM + lane*16;
    __half* wv = g_v + (size_t)row*DIM + lane*16;
    *(uint4*)wq = *(uint4*)&qo[0];  *(uint4*)(wq+8) = *(uint4*)&qo[4];
    *(uint4*)wk = *(uint4*)&ko[0];  *(uint4*)(wk+8) = *(uint4*)&ko[4];
    *(uint4*)wv = v0;               *(uint4*)(wv+8) = v1;
}

// ---------------- colsum of p = e/Z: single streaming pass ----------------
#define SC_ROWS 32
__global__ void colsum_k()
{
    int row0 = blockIdx.x * SC_ROWS;
    int b = row0 >> 11;
    int tid = threadIdx.x;            // 256
    int c0 = tid * 8;
    __shared__ float zinv[SC_ROWS];
    if (tid < SC_ROWS) zinv[tid] = __frcp_rn(g_Z[row0 + tid]);
    __syncthreads();
    const __nv_bfloat16* base = g_expsb + (size_t)row0*SEQ + c0;
    float acc[8] = {0,0,0,0,0,0,0,0};
    #pragma unroll 4
    for (int r = 0; r < SC_ROWS; r++){
        uint4 u = *(const uint4*)(base + (size_t)r*SEQ);
        __nv_bfloat162* h = (__nv_bfloat162*)&u;
        float iz = zinv[r];
        #pragma unroll
        for (int i=0;i<4;i++){
            float2 f = __bfloat1622float2(h[i]);
            acc[2*i]   += f.x * iz;
            acc[2*i+1] += f.y * iz;
        }
    }
    float* wb = g_wbar + b*SEQ + c0;
    #pragma unroll
    for (int i=0;i<8;i++) atomicAdd(wb + i, acc[i]);
}

// ---------------- final reduction (fp16 x and v) ----------------
__global__ void final_acc_k()
{
    int b = blockIdx.y, c = blockIdx.x;
    int t = threadIdx.x;              // 256, half2 lanes
    size_t base2 = (((size_t)b*SEQ + (size_t)c*128)*DIM >> 1) + t;
    const __half2* xh2 = (const __half2*)g_xh;
    const __half2* v2  = (const __half2*)g_v;
    const float* wb = g_wbar + b*SEQ + c*128;
    float ax=0.f, ay=0.f;
    #pragma unroll 4
    for (int s=0;s<128;s++){
        float2 xf = __half22float2(xh2[base2 + (size_t)s*(DIM/2)]);
        float2 vf = __half22float2(v2 [base2 + (size_t)s*(DIM/2)]);
        float w = wb[s];
        ax += xf.x + w*vf.x;
        ay += xf.y + w*vf.y;
    }
    g_part[(b*16+c)*DIM + 2*t]   = ax;
    g_part[(b*16+c)*DIM + 2*t+1] = ay;
}
__global__ void final_reduce_k(float* __restrict__ out)
{
    int b = blockIdx.x, d = threadIdx.x;
    float a = 0.f;
    #pragma unroll
    for (int c=0;c<16;c++) a += g_part[(b*16+c)*DIM + d];
    out[b*DIM + d] = a * (1.f/SEQ);
}

// ---------------- launch ----------------
extern "C" void kernel_launch(void* const* d_in, const int* in_sizes, int n_in,
                              void* d_out, int out_size)
{
    const float* x      = (const float*)d_in[0];
    const float* conv_w = (const float*)d_in[1];
    const float* conv_b = (const float*)d_in[2];
    const float* pre_g  = (const float*)d_in[3];
    const float* q_g    = (const float*)d_in[4];
    const float* k_g    = (const float*)d_in[5];
    const float* Wq     = (const float*)d_in[6];
    const float* Wk     = (const float*)d_in[7];
    const float* Wv     = (const float*)d_in[8];
    float* out = (float*)d_out;

    __half *xh, *wch, *wqkvh, *xconvh, *xnorm, *qkvh, *q, *k;
    __nv_bfloat16 *expsb;
    cudaGetSymbolAddress((void**)&xh, g_xh);
    cudaGetSymbolAddress((void**)&wch, g_wch);
    cudaGetSymbolAddress((void**)&wqkvh, g_wqkvh);
    cudaGetSymbolAddress((void**)&xconvh, g_xconvh);
    cudaGetSymbolAddress((void**)&xnorm, g_xnorm);
    cudaGetSymbolAddress((void**)&qkvh, g_qkvh);
    cudaGetSymbolAddress((void**)&q, g_q);
    cudaGetSymbolAddress((void**)&k, g_k);
    cudaGetSymbolAddress((void**)&expsb, g_expsb);

    cudaFuncSetAttribute(mma_gemm_k<0>, cudaFuncAttributeMaxDynamicSharedMemorySize, GSMEM);
    cudaFuncSetAttribute(mma_gemm_k<1>, cudaFuncAttributeMaxDynamicSharedMemorySize, GSMEM);
    cudaFuncSetAttribute(mma_gemm_k<2>, cudaFuncAttributeMaxDynamicSharedMemorySize, GSMEM);

    // merged setup: x->fp16 (+zero wbar/Z) | weight prep | rope tables, one launch
    setup_k<<<SETUP_BLKS, 256>>>(x, conv_w, Wq, Wk, Wv);

    // conv: M=16384, N=512, K=1536
    mma_gemm_k<1><<<dim3(DIM/256, MR/128), 256, GSMEM>>>(xh, wch, xconvh, DIM, 3*DIM, 1.f);
    rmsnorm_pre_k<<<MR/8, 256>>>(pre_g, conv_b);

    // qkv: M=16384, N=1536, K=512
    mma_gemm_k<0><<<dim3(3*DIM/256, MR/128), 256, GSMEM>>>(xnorm, wqkvh, qkvh, 3*DIM, DIM, 1.f);
    qkv_post_k<<<MR/8, 256>>>(q_g, k_g);

    // scores: per-batch NT, M=N=2048, K=512; epilogue = exp -> bf16 + row sums
    mma_gemm_k<2><<<dim3(SEQ/256, SEQ/128, BATCH), 256, GSMEM>>>(q, k, (__half*)expsb, SEQ, DIM,
                                                                 0.044194173824159216f);
    colsum_k<<<MR/SC_ROWS, 256>>>();
    final_acc_k<<<dim3(16, BATCH), 256>>>();
    final_reduce_k<<<BATCH, DIM>>>(out);
}

// round 16
// speedup vs baseline: 1.1667x; 1.1667x over previous
#include <cuda_runtime.h>
#include <cuda_fp16.h>
#include <cuda_bf16.h>
#include <cstdint>
#include <math.h>
#include <mma.h>

using namespace nvcuda;

#define BATCH 8
#define SEQ   2048
#define DIM   512
#define MR    (BATCH*SEQ)
#define HALF  (DIM/2)

// ---------------- static scratch ----------------
__device__ __half g_xh[(size_t)MR*DIM];         // x fp16 (im2col source + final acc)
__device__ __half g_wch[3*DIM*DIM];             // conv weights [dout][k=1536] K-major fp16
__device__ __half g_wqkvh[3*DIM*DIM];           // concat(Wq,Wk,Wv) [e=1536][d=512] fp16
__device__ __half g_xconvh[(size_t)MR*DIM];     // conv output fp16 (pre-bias)
__device__ __half g_xnorm[(size_t)MR*DIM];      // rmsnorm(conv+bias) fp16
__device__ __half g_qkvh[(size_t)MR*3*DIM];     // raw q|k|v fp16
__device__ __half g_q[(size_t)MR*DIM];          // normed+rope'd q fp16
__device__ __half g_k[(size_t)MR*DIM];          // normed+rope'd k fp16
__device__ __half g_v[(size_t)MR*DIM];          // v fp16
__device__ __nv_bfloat16 g_expsb[(size_t)BATCH*SEQ*SEQ]; // exp(logit) bf16
__device__ float  g_Z[MR];                      // row sums of exp
__device__ float  g_wbar[MR];
__device__ double g_inv[HALF];
__device__ float  g_cos[SEQ*HALF];
__device__ float  g_sin[SEQ*HALF];
__device__ float  g_part[BATCH*16*DIM];

// ---------------- helpers ----------------
__device__ __forceinline__ uint32_t smem_u32(const void* p){
    uint32_t a;
    asm("{ .reg .u64 t; cvta.to.shared.u64 t, %1; cvt.u32.u64 %0, t; }" : "=r"(a) : "l"(p));
    return a;
}
__device__ __forceinline__ void cp_async16(uint32_t dst, const void* src, bool pred){
    int sz = pred ? 16 : 0;   // ZFILL when masked
    asm volatile("cp.async.cg.shared.global [%0], [%1], 16, %2;"
                 :: "r"(dst), "l"(src), "r"(sz));
}
__device__ __forceinline__ void cp_async_commit(){
    asm volatile("cp.async.commit_group;" ::: "memory");
}
template<int N>
__device__ __forceinline__ void cp_async_wait(){
    asm volatile("cp.async.wait_group %0;" :: "n"(N) : "memory");
}
__device__ __forceinline__ float warp_sum(float v){
    #pragma unroll
    for (int o=16;o;o>>=1) v += __shfl_xor_sync(0xffffffffu, v, o);
    return v;
}
// FMA-pipe exp. |rel err| ~2e-5.
__device__ __forceinline__ float fast_exp(float x){
    float t = x * 1.4426950408889634f;
    t = fmaxf(t, -125.0f);
    float fl = floorf(t);
    float f = t - fl;
    float p = 1.5403530e-4f;
    p = fmaf(p, f, 1.3333558e-3f);
    p = fmaf(p, f, 9.6181291e-3f);
    p = fmaf(p, f, 5.5504109e-2f);
    p = fmaf(p, f, 2.4022651e-1f);
    p = fmaf(p, f, 6.9314718e-1f);
    p = fmaf(p, f, 1.0f);
    int i = (int)fl;
    return p * __int_as_float((i + 127) << 23);
}

// ---------------- input conversion (+ wbar/Z zero) / weight re-layout ----------------
__global__ void cvt_x_k(const float* __restrict__ x)
{
    size_t flat = (size_t)blockIdx.x*256 + threadIdx.x;
    size_t i = flat * 8;
    float4 v0 = *(const float4*)&x[i];
    float4 v1 = *(const float4*)&x[i+4];
    __half2 h[4] = { __floats2half2_rn(v0.x,v0.y), __floats2half2_rn(v0.z,v0.w),
                     __floats2half2_rn(v1.x,v1.y), __floats2half2_rn(v1.z,v1.w) };
    *(uint4*)&g_xh[i] = *(uint4*)h;
    if (flat < MR) { g_wbar[flat] = 0.f; g_Z[flat] = 0.f; }
}

__global__ void prep_weights(const float* __restrict__ conv_w,
                             const float* __restrict__ Wq,
                             const float* __restrict__ Wk,
                             const float* __restrict__ Wv)
{
    int idx = blockIdx.x*256 + threadIdx.x;
    if (idx >= 3*DIM*DIM) return;
    {   // conv: [dout][kk], kk = t*512 + din
        int kk   = idx % (3*DIM);
        int dout = idx / (3*DIM);
        int din  = kk % DIM;
        int t    = kk / DIM;
        g_wch[idx] = __float2half_rn(conv_w[(dout*DIM + din)*3 + t]);
    }
    {   // qkv concat
        float w = (idx < DIM*DIM) ? Wq[idx]
                : (idx < 2*DIM*DIM) ? Wk[idx - DIM*DIM]
                : Wv[idx - 2*DIM*DIM];
        g_wqkvh[idx] = __float2half_rn(w);
    }
}

// fp64 pow only 256 times; tables via double range-reduction + float sincos.
__global__ void rope_inv_k()
{
    int i = threadIdx.x;
    g_inv[i] = pow(10000.0, -((double)(2*i)) / 512.0);
}
__global__ void rope_tables_k()
{
    int i = threadIdx.x;   // 0..255
    int s = blockIdx.x;    // 0..2047
    double arg = (double)s * g_inv[i];
    const double TWO_PI = 6.283185307179586476925;
    double red = arg - rint(arg * (1.0/TWO_PI)) * TWO_PI;   // [-pi, pi]
    float rf = (float)red;
    float sn, cs;
    __sincosf(rf, &sn, &cs);
    g_cos[s*HALF + i] = cs;
    g_sin[s*HALF + i] = sn;
}

// ---------------- fp16 WMMA GEMM: block 128x256x32, warp tile 64x64 ----------------
// C[M,N] = A[M,K] * B[N,K]^T, f32 accumulate.
// MODE 0: generic (fp16 C).  MODE 1: A = implicit im2col (conv, fp16 C).
// MODE 2: batched via z; epilogue computes exp(scale*acc), stores bf16, row-sums into g_Z.
#define TLDH   40
#define A_BYT  (128*TLDH*2)          // 10240
#define STG_B  ((128+256)*TLDH*2)    // 30720
#define ELD    260                   // epilogue f32 tile ld (64 x 260 x 4 = 66560)
#define GSMEM  (3*STG_B)             // 92160

template<int MODE>
__global__ __launch_bounds__(256,1) void mma_gemm_k(
    const __half* __restrict__ Ah, const __half* __restrict__ Bh,
    __half* __restrict__ Ch, int Nd, int Kd, float scale)
{
    extern __shared__ __half smh[];
    const uint32_t sb = smem_u32(smh);
    const int tid = threadIdx.x;
    const int wid = tid >> 5, lane = tid & 31;
    const int wm = wid & 1, wn = wid >> 1;           // 2 x 4 warps, warp tile 64x64
    const int bm = blockIdx.y*128, bn = blockIdx.x*256;
    float* Zp = nullptr;
    if (MODE == 2) {
        size_t z = blockIdx.z;
        Ah += z * (size_t)SEQ * DIM;
        Bh += z * (size_t)SEQ * DIM;
        Ch += z * (size_t)SEQ * SEQ;
        Zp = g_Z + z * SEQ;
    }

    wmma::fragment<wmma::accumulator,16,16,16,float> acc[4][4];
    #pragma unroll
    for (int i=0;i<4;i++)
        #pragma unroll
        for (int j=0;j<4;j++) wmma::fill_fragment(acc[i][j], 0.f);

    const int nIter = Kd / 32;

    auto load_tiles = [&](int it, int stg){
        const int k0 = it*32;
        const uint32_t abase = sb + stg*STG_B;
        const uint32_t bbase = abase + A_BYT;
        // A: 128 rows x 32 halfs
        #pragma unroll
        for (int l=0;l<2;l++){
            int i   = l*256 + tid;
            int row = i >> 2;
            int kq  = (i & 3) * 8;
            const __half* src; bool pred = true;
            if (MODE == 1) {
                int gm = bm + row;
                int s  = gm & (SEQ-1);
                int kg = k0 + kq;
                int t  = kg >> 9;
                pred = !((s==0 && t==0) || (s==SEQ-1 && t==2));
                src = pred ? (Ah + (size_t)gm*DIM + kg - DIM) : Ah;
            } else {
                src = Ah + (size_t)(bm+row)*Kd + k0 + kq;
            }
            cp_async16(abase + (row*TLDH + kq)*2, src, pred);
        }
        // B: 256 rows x 32 halfs
        #pragma unroll
        for (int l=0;l<4;l++){
            int i   = l*256 + tid;
            int row = i >> 2;
            int kq  = (i & 3) * 8;
            cp_async16(bbase + (row*TLDH + kq)*2,
                       Bh + (size_t)(bn+row)*Kd + k0 + kq, true);
        }
    };

    load_tiles(0, 0); cp_async_commit();
    load_tiles(1, 1); cp_async_commit();

    for (int it = 0; it < nIter; ++it) {
        cp_async_wait<1>();
        __syncthreads();
        const int stg = it % 3;
        const __half* Ab = smh + stg*(STG_B/2);
        const __half* Bb = Ab + 128*TLDH;
        #pragma unroll
        for (int ks = 0; ks < 2; ks++) {
            wmma::fragment<wmma::matrix_b,16,16,16,__half,wmma::col_major> bf[4];
            #pragma unroll
            for (int j=0;j<4;j++)
                wmma::load_matrix_sync(bf[j], Bb + (wn*64 + j*16)*TLDH + ks*16, TLDH);
            #pragma unroll
            for (int i=0;i<4;i++){
                wmma::fragment<wmma::matrix_a,16,16,16,__half,wmma::row_major> af;
                wmma::load_matrix_sync(af, Ab + (wm*64 + i*16)*TLDH + ks*16, TLDH);
                #pragma unroll
                for (int j=0;j<4;j++)
                    wmma::mma_sync(acc[i][j], af, bf[j], acc[i][j]);
            }
        }
        if (it + 2 < nIter) load_tiles(it+2, (it+2)%3);
        cp_async_commit();
    }

    // epilogue via 64x260 f32 smem tile, two M-half passes
    cp_async_wait<0>();
    __syncthreads();
    float* eb = (float*)smh;
    #pragma unroll
    for (int h=0; h<2; h++){
        if (wm == h) {
            #pragma unroll
            for (int i=0;i<4;i++)
                #pragma unroll
                for (int j=0;j<4;j++)
                    wmma::store_matrix_sync(eb + (i*16)*ELD + wn*64 + j*16,
                                            acc[i][j], ELD, wmma::mem_row_major);
        }
        __syncthreads();
        #pragma unroll
        for (int p=0;p<8;p++){
            int e = p*256 + tid;          // 0..2047 chunks of 8 cols
            int row = e >> 5;             // tid 0..31 of each warp share one row
            int c0 = (e & 31) * 8;
            float4 a = *(float4*)&eb[row*ELD + c0];
            float4 b = *(float4*)&eb[row*ELD + c0 + 4];
            if (MODE == 2) {
                float ev[8] = { fast_exp(a.x*scale), fast_exp(a.y*scale),
                                fast_exp(a.z*scale), fast_exp(a.w*scale),
                                fast_exp(b.x*scale), fast_exp(b.y*scale),
                                fast_exp(b.z*scale), fast_exp(b.w*scale) };
                float s = ev[0]+ev[1]+ev[2]+ev[3]+ev[4]+ev[5]+ev[6]+ev[7];
                s = warp_sum(s);
                if (lane == 0) atomicAdd(&Zp[bm + h*64 + row], s);
                __nv_bfloat162 bb[4] = {
                    __floats2bfloat162_rn(ev[0],ev[1]), __floats2bfloat162_rn(ev[2],ev[3]),
                    __floats2bfloat162_rn(ev[4],ev[5]), __floats2bfloat162_rn(ev[6],ev[7]) };
                *(uint4*)&Ch[(size_t)(bm + h*64 + row)*Nd + bn + c0] = *(uint4*)bb;
            } else {
                __half2 hh[4] = { __floats2half2_rn(a.x,a.y), __floats2half2_rn(a.z,a.w),
                                  __floats2half2_rn(b.x,b.y), __floats2half2_rn(b.z,b.w) };
                *(uint4*)&Ch[(size_t)(bm + h*64 + row)*Nd + bn + c0] = *(uint4*)hh;
            }
        }
        __syncthreads();
    }
}

// ---------------- rmsnorm(conv + bias) -> fp16, warp per row ----------------
__global__ void rmsnorm_pre_k(const float* __restrict__ pre_g,
                              const float* __restrict__ conv_b)
{
    int row  = blockIdx.x*8 + (threadIdx.x >> 5);
    int lane = threadIdx.x & 31;
    const __half* r = g_xconvh + (size_t)row*DIM + lane*16;
    uint4 u0 = *(const uint4*)r;
    uint4 u1 = *(const uint4*)(r + 8);
    float4 b0 = *(const float4*)&conv_b[lane*16];
    float4 b1 = *(const float4*)&conv_b[lane*16+4];
    float4 b2 = *(const float4*)&conv_b[lane*16+8];
    float4 b3 = *(const float4*)&conv_b[lane*16+12];
    __half2* h0 = (__half2*)&u0;
    __half2* h1 = (__half2*)&u1;
    float v[16];
    #pragma unroll
    for (int i=0;i<4;i++){
        float2 f = __half22float2(h0[i]); v[2*i]=f.x; v[2*i+1]=f.y;
        float2 g = __half22float2(h1[i]); v[8+2*i]=g.x; v[8+2*i+1]=g.y;
    }
    float bias[16] = {b0.x,b0.y,b0.z,b0.w,b1.x,b1.y,b1.z,b1.w,
                      b2.x,b2.y,b2.z,b2.w,b3.x,b3.y,b3.z,b3.w};
    float ss = 0.f;
    #pragma unroll
    for (int i=0;i<16;i++){ v[i] += bias[i]; ss += v[i]*v[i]; }
    ss = warp_sum(ss);
    float rr = rsqrtf(ss * (1.f/DIM) + 1e-6f);
    float4 g0 = *(const float4*)&pre_g[lane*16];
    float4 g1 = *(const float4*)&pre_g[lane*16+4];
    float4 g2 = *(const float4*)&pre_g[lane*16+8];
    float4 g3 = *(const float4*)&pre_g[lane*16+12];
    float gg[16] = {g0.x,g0.y,g0.z,g0.w,g1.x,g1.y,g1.z,g1.w,
                    g2.x,g2.y,g2.z,g2.w,g3.x,g3.y,g3.z,g3.w};
    __half2 o[8];
    #pragma unroll
    for (int i=0;i<8;i++)
        o[i] = __floats2half2_rn(v[2*i]*rr*gg[2*i], v[2*i+1]*rr*gg[2*i+1]);
    __half* w = g_xnorm + (size_t)row*DIM + lane*16;
    *(uint4*)w       = *(uint4*)&o[0];
    *(uint4*)(w + 8) = *(uint4*)&o[4];
}

// ---------------- rmsnorm + rope on q/k -> fp16, copy v; warp per row ----------------
__global__ void qkv_post_k(const float* __restrict__ q_g, const float* __restrict__ k_g)
{
    int row  = blockIdx.x*8 + (threadIdx.x >> 5);
    int lane = threadIdx.x & 31;
    int s = row & (SEQ-1);
    const __half* r = g_qkvh + (size_t)row*3*DIM + lane*16;
    uint4 q0 = *(const uint4*)r;
    uint4 q1 = *(const uint4*)(r + 8);
    uint4 k0 = *(const uint4*)(r + DIM);
    uint4 k1 = *(const uint4*)(r + DIM + 8);
    uint4 v0 = *(const uint4*)(r + 2*DIM);
    uint4 v1 = *(const uint4*)(r + 2*DIM + 8);
    float q[16], k[16];
    {
        __half2* hq0=(__half2*)&q0; __half2* hq1=(__half2*)&q1;
        __half2* hk0=(__half2*)&k0; __half2* hk1=(__half2*)&k1;
        #pragma unroll
        for (int i=0;i<4;i++){
            float2 f;
            f=__half22float2(hq0[i]); q[2*i]=f.x; q[2*i+1]=f.y;
            f=__half22float2(hq1[i]); q[8+2*i]=f.x; q[8+2*i+1]=f.y;
            f=__half22float2(hk0[i]); k[2*i]=f.x; k[2*i+1]=f.y;
            f=__half22float2(hk1[i]); k[8+2*i]=f.x; k[8+2*i+1]=f.y;
        }
    }
    float sq=0.f, sk=0.f;
    #pragma unroll
    for (int i=0;i<16;i++){ sq += q[i]*q[i]; sk += k[i]*k[i]; }
    sq = warp_sum(sq); sk = warp_sum(sk);
    float rq = rsqrtf(sq * (1.f/DIM) + 1e-6f);
    float rk = rsqrtf(sk * (1.f/DIM) + 1e-6f);

    float4 c0 = *(const float4*)&g_cos[s*HALF + lane*8];
    float4 c1 = *(const float4*)&g_cos[s*HALF + lane*8 + 4];
    float4 s0 = *(const float4*)&g_sin[s*HALF + lane*8];
    float4 s1 = *(const float4*)&g_sin[s*HALF + lane*8 + 4];
    float cs[8] = {c0.x,c0.y,c0.z,c0.w,c1.x,c1.y,c1.z,c1.w};
    float sn[8] = {s0.x,s0.y,s0.z,s0.w,s1.x,s1.y,s1.z,s1.w};
    float4 qg0 = *(const float4*)&q_g[lane*16];
    float4 qg1 = *(const float4*)&q_g[lane*16+4];
    float4 qg2 = *(const float4*)&q_g[lane*16+8];
    float4 qg3 = *(const float4*)&q_g[lane*16+12];
    float4 kg0 = *(const float4*)&k_g[lane*16];
    float4 kg1 = *(const float4*)&k_g[lane*16+4];
    float4 kg2 = *(const float4*)&k_g[lane*16+8];
    float4 kg3 = *(const float4*)&k_g[lane*16+12];
    float qg[16] = {qg0.x,qg0.y,qg0.z,qg0.w,qg1.x,qg1.y,qg1.z,qg1.w,
                    qg2.x,qg2.y,qg2.z,qg2.w,qg3.x,qg3.y,qg3.z,qg3.w};
    float kg[16] = {kg0.x,kg0.y,kg0.z,kg0.w,kg1.x,kg1.y,kg1.z,kg1.w,
                    kg2.x,kg2.y,kg2.z,kg2.w,kg3.x,kg3.y,kg3.z,kg3.w};

    __half2 qo[8], ko[8];
    #pragma unroll
    for (int j=0;j<8;j++){
        float x0 = q[2*j]*rq*qg[2*j], x1 = q[2*j+1]*rq*qg[2*j+1];
        qo[j] = __floats2half2_rn(x0*cs[j] - x1*sn[j], x0*sn[j] + x1*cs[j]);
        float y0 = k[2*j]*rk*kg[2*j], y1 = k[2*j+1]*rk*kg[2*j+1];
        ko[j] = __floats2half2_rn(y0*cs[j] - y1*sn[j], y0*sn[j] + y1*cs[j]);
    }
    __half* wq = g_q + (size_t)row*DIM + lane*16;
    __half* wk = g_k + (size_t)row*DIM + lane*16;
    __half* wv = g_v + (size_t)row*DIM + lane*16;
    *(uint4*)wq = *(uint4*)&qo[0];  *(uint4*)(wq+8) = *(uint4*)&qo[4];
    *(uint4*)wk = *(uint4*)&ko[0];  *(uint4*)(wk+8) = *(uint4*)&ko[4];
    *(uint4*)wv = v0;               *(uint4*)(wv+8) = v1;
}

// ---------------- colsum of p = e/Z: single streaming pass ----------------
#define SC_ROWS 32
__global__ void colsum_k()
{
    int row0 = blockIdx.x * SC_ROWS;
    int b = row0 >> 11;
    int tid = threadIdx.x;            // 256
    int c0 = tid * 8;
    __shared__ float zinv[SC_ROWS];
    if (tid < SC_ROWS) zinv[tid] = __frcp_rn(g_Z[row0 + tid]);
    __syncthreads();
    const __nv_bfloat16* base = g_expsb + (size_t)row0*SEQ + c0;
    float acc[8] = {0,0,0,0,0,0,0,0};
    #pragma unroll 4
    for (int r = 0; r < SC_ROWS; r++){
        uint4 u = *(const uint4*)(base + (size_t)r*SEQ);
        __nv_bfloat162* h = (__nv_bfloat162*)&u;
        float iz = zinv[r];
        #pragma unroll
        for (int i=0;i<4;i++){
            float2 f = __bfloat1622float2(h[i]);
            acc[2*i]   += f.x * iz;
            acc[2*i+1] += f.y * iz;
        }
    }
    float* wb = g_wbar + b*SEQ + c0;
    #pragma unroll
    for (int i=0;i<8;i++) atomicAdd(wb + i, acc[i]);
}

// ---------------- final reduction (fp16 x and v) ----------------
__global__ void final_acc_k()
{
    int b = blockIdx.y, c = blockIdx.x;
    int t = threadIdx.x;              // 256, half2 lanes
    size_t base2 = (((size_t)b*SEQ + (size_t)c*128)*DIM >> 1) + t;
    const __half2* xh2 = (const __half2*)g_xh;
    const __half2* v2  = (const __half2*)g_v;
    const float* wb = g_wbar + b*SEQ + c*128;
    float ax=0.f, ay=0.f;
    #pragma unroll 4
    for (int s=0;s<128;s++){
        float2 xf = __half22float2(xh2[base2 + (size_t)s*(DIM/2)]);
        float2 vf = __half22float2(v2 [base2 + (size_t)s*(DIM/2)]);
        float w = wb[s];
        ax += xf.x + w*vf.x;
        ay += xf.y + w*vf.y;
    }
    g_part[(b*16+c)*DIM + 2*t]   = ax;
    g_part[(b*16+c)*DIM + 2*t+1] = ay;
}
__global__ void final_reduce_k(float* __restrict__ out)
{
    int b = blockIdx.x, d = threadIdx.x;
    float a = 0.f;
    #pragma unroll
    for (int c=0;c<16;c++) a += g_part[(b*16+c)*DIM + d];
    out[b*DIM + d] = a * (1.f/SEQ);
}

// ---------------- launch ----------------
extern "C" void kernel_launch(void* const* d_in, const int* in_sizes, int n_in,
                              void* d_out, int out_size)
{
    const float* x      = (const float*)d_in[0];
    const float* conv_w = (const float*)d_in[1];
    const float* conv_b = (const float*)d_in[2];
    const float* pre_g  = (const float*)d_in[3];
    const float* q_g    = (const float*)d_in[4];
    const float* k_g    = (const float*)d_in[5];
    const float* Wq     = (const float*)d_in[6];
    const float* Wk     = (const float*)d_in[7];
    const float* Wv     = (const float*)d_in[8];
    float* out = (float*)d_out;

    __half *xh, *wch, *wqkvh, *xconvh, *xnorm, *qkvh, *q, *k;
    __nv_bfloat16 *expsb;
    cudaGetSymbolAddress((void**)&xh, g_xh);
    cudaGetSymbolAddress((void**)&wch, g_wch);
    cudaGetSymbolAddress((void**)&wqkvh, g_wqkvh);
    cudaGetSymbolAddress((void**)&xconvh, g_xconvh);
    cudaGetSymbolAddress((void**)&xnorm, g_xnorm);
    cudaGetSymbolAddress((void**)&qkvh, g_qkvh);
    cudaGetSymbolAddress((void**)&q, g_q);
    cudaGetSymbolAddress((void**)&k, g_k);
    cudaGetSymbolAddress((void**)&expsb, g_expsb);

    cudaFuncSetAttribute(mma_gemm_k<0>, cudaFuncAttributeMaxDynamicSharedMemorySize, GSMEM);
    cudaFuncSetAttribute(mma_gemm_k<1>, cudaFuncAttributeMaxDynamicSharedMemorySize, GSMEM);
    cudaFuncSetAttribute(mma_gemm_k<2>, cudaFuncAttributeMaxDynamicSharedMemorySize, GSMEM);

    cvt_x_k<<<MR*DIM/8/256, 256>>>(x);
    prep_weights<<<(3*DIM*DIM + 255)/256, 256>>>(conv_w, Wq, Wk, Wv);
    rope_inv_k<<<1, HALF>>>();
    rope_tables_k<<<SEQ, HALF>>>();

    // conv: M=16384, N=512, K=1536
    mma_gemm_k<1><<<dim3(DIM/256, MR/128), 256, GSMEM>>>(xh, wch, xconvh, DIM, 3*DIM, 1.f);
    rmsnorm_pre_k<<<MR/8, 256>>>(pre_g, conv_b);

    // qkv: M=16384, N=1536, K=512
    mma_gemm_k<0><<<dim3(3*DIM/256, MR/128), 256, GSMEM>>>(xnorm, wqkvh, qkvh, 3*DIM, DIM, 1.f);
    qkv_post_k<<<MR/8, 256>>>(q_g, k_g);

    // scores: per-batch NT, M=N=2048, K=512; epilogue = exp -> bf16 + row sums
    mma_gemm_k<2><<<dim3(SEQ/256, SEQ/128, BATCH), 256, GSMEM>>>(q, k, (__half*)expsb, SEQ, DIM,
                                                                 0.044194173824159216f);
    colsum_k<<<MR/SC_ROWS, 256>>>();
    final_acc_k<<<dim3(16, BATCH), 256>>>();
    final_reduce_k<<<BATCH, DIM>>>(out);
}